// round 7
// baseline (speedup 1.0000x reference)
#include <cuda_runtime.h>
#include <math.h>

#define T_  512
#define B_  64
#define E_  256
#define H_  256
#define TB_ (T_ * B_)          // 32768
#define CLU 16                 // CTAs per cluster (non-portable size)
#define BGR 8                  // batch elements per cluster (two quads)

// ---------------- static device scratch ----------------
__device__ float g_Q  [TB_ * E_];
__device__ float g_K  [TB_ * E_];
__device__ float g_S  [B_ * T_ * T_];
__device__ float g_CTX[TB_ * E_];
__device__ float g_CP [TB_ * H_];
__device__ float g_PRE[(long)TB_ * 4 * H_];
__device__ float g_Wall[512 * 1024];       // packed [Wf|Wi|Wu|Wo] as (512, 1024)
__device__ float g_ball[1024];
__device__ float g_WhC[CLU * 256 * 16 * 4];// recurrent W: [rank][k][jl16][gate4]

// ---------------- bf16 2-split helpers ----------------
__device__ __forceinline__ void split_bf2(float e, float o, unsigned& hi, unsigned& lo)
{
    unsigned h;
    asm("cvt.rn.bf16x2.f32 %0, %1, %2;" : "=r"(h) : "f"(o), "f"(e));
    float eh = __uint_as_float(h << 16);
    float oh = __uint_as_float(h & 0xffff0000u);
    unsigned l;
    asm("cvt.rn.bf16x2.f32 %0, %1, %2;" : "=r"(l) : "f"(o - oh), "f"(e - eh));
    hi = h; lo = l;
}

#define MMA_BF16(c, a, b)                                                          \
    asm volatile("mma.sync.aligned.m16n8k16.row.col.f32.bf16.bf16.f32 "            \
                 "{%0,%1,%2,%3},{%4,%5,%6,%7},{%8,%9},{%0,%1,%2,%3};"              \
                 : "+f"(c[0]), "+f"(c[1]), "+f"(c[2]), "+f"(c[3])                  \
                 : "r"(a[0]), "r"(a[1]), "r"(a[2]), "r"(a[3]),                     \
                   "r"(b[0]), "r"(b[1]))

// ---------------- tensor-core bf16 GEMM, 128x128x16 tile, 3x split -----------
template<bool NT, bool BIAS, bool CONCAT>
__global__ void __launch_bounds__(256, 1) gemm_tc(
    const float* __restrict__ A, const float* __restrict__ A2,
    const float* __restrict__ B, float* __restrict__ C,
    const float* __restrict__ bias,
    int M, int N, int K, int lda, int ldb, int ldc,
    long sA, long sB, long sC)
{
    A += (long)blockIdx.z * sA;
    B += (long)blockIdx.z * sB;
    C += (long)blockIdx.z * sC;

    __shared__ unsigned As_hi[8][136], As_lo[8][136];
    __shared__ unsigned Bs_hi[8][136], Bs_lo[8][136];

    const int tid  = threadIdx.x;
    const int lane = tid & 31;
    const int warp = tid >> 5;
    const int m0 = blockIdx.y * 128;
    const int n0 = blockIdx.x * 128;
    const int wm = (warp >> 2) * 64;
    const int wn = (warp & 3) * 32;
    const int gq = lane >> 2;
    const int tg = lane & 3;

    const int ar = tid & 127;
    const int aq = (tid >> 7) * 4;
    const int bkr = tid >> 5;
    const int bn  = (tid & 31) * 4;
    const int bn_t = tid & 127;
    const int bq   = (tid >> 7) * 4;

    float acc[4][4][4];
    #pragma unroll
    for (int i = 0; i < 4; ++i)
        #pragma unroll
        for (int j = 0; j < 4; ++j)
            #pragma unroll
            for (int q = 0; q < 4; ++q) acc[i][j][q] = 0.f;

    float4 va0, va1, vb0, vb1;
    auto load_tile = [&](int k0) {
        const float* Ab = A;
        int kc = k0;
        if (CONCAT) { if (k0 >= 256) { Ab = A2; kc = k0 - 256; } }
        va0 = *(const float4*)(Ab + (long)(m0 + ar) * lda + kc + aq);
        va1 = *(const float4*)(Ab + (long)(m0 + ar) * lda + kc + aq + 8);
        if (NT) {
            vb0 = *(const float4*)(B + (long)(n0 + bn_t) * ldb + k0 + bq);
            vb1 = *(const float4*)(B + (long)(n0 + bn_t) * ldb + k0 + bq + 8);
        } else {
            vb0 = *(const float4*)(B + (long)(k0 + 2 * bkr) * ldb + n0 + bn);
            vb1 = *(const float4*)(B + (long)(k0 + 2 * bkr + 1) * ldb + n0 + bn);
        }
    };

    load_tile(0);

    for (int k0 = 0; k0 < K; k0 += 16) {
        __syncthreads();
        {
            int kp = aq >> 1;
            split_bf2(va0.x, va0.y, As_hi[kp    ][ar], As_lo[kp    ][ar]);
            split_bf2(va0.z, va0.w, As_hi[kp + 1][ar], As_lo[kp + 1][ar]);
            split_bf2(va1.x, va1.y, As_hi[kp + 4][ar], As_lo[kp + 4][ar]);
            split_bf2(va1.z, va1.w, As_hi[kp + 5][ar], As_lo[kp + 5][ar]);
            if (NT) {
                int bp = bq >> 1;
                split_bf2(vb0.x, vb0.y, Bs_hi[bp    ][bn_t], Bs_lo[bp    ][bn_t]);
                split_bf2(vb0.z, vb0.w, Bs_hi[bp + 1][bn_t], Bs_lo[bp + 1][bn_t]);
                split_bf2(vb1.x, vb1.y, Bs_hi[bp + 4][bn_t], Bs_lo[bp + 4][bn_t]);
                split_bf2(vb1.z, vb1.w, Bs_hi[bp + 5][bn_t], Bs_lo[bp + 5][bn_t]);
            } else {
                uint4 h4, l4;
                split_bf2(vb0.x, vb1.x, h4.x, l4.x);
                split_bf2(vb0.y, vb1.y, h4.y, l4.y);
                split_bf2(vb0.z, vb1.z, h4.z, l4.z);
                split_bf2(vb0.w, vb1.w, h4.w, l4.w);
                *(uint4*)&Bs_hi[bkr][bn] = h4;
                *(uint4*)&Bs_lo[bkr][bn] = l4;
            }
        }
        __syncthreads();

        int kn = (k0 + 16 < K) ? k0 + 16 : k0;
        load_tile(kn);

        unsigned ah[4][4], al[4][4], bh[4][2], bl[4][2];
        #pragma unroll
        for (int i = 0; i < 4; ++i) {
            int r = wm + i * 16 + gq;
            ah[i][0] = As_hi[tg    ][r];
            ah[i][1] = As_hi[tg    ][r + 8];
            ah[i][2] = As_hi[tg + 4][r];
            ah[i][3] = As_hi[tg + 4][r + 8];
            al[i][0] = As_lo[tg    ][r];
            al[i][1] = As_lo[tg    ][r + 8];
            al[i][2] = As_lo[tg + 4][r];
            al[i][3] = As_lo[tg + 4][r + 8];
        }
        #pragma unroll
        for (int j = 0; j < 4; ++j) {
            int n = wn + j * 8 + gq;
            bh[j][0] = Bs_hi[tg    ][n];
            bh[j][1] = Bs_hi[tg + 4][n];
            bl[j][0] = Bs_lo[tg    ][n];
            bl[j][1] = Bs_lo[tg + 4][n];
        }
        #pragma unroll
        for (int i = 0; i < 4; ++i)
            #pragma unroll
            for (int j = 0; j < 4; ++j) {
                MMA_BF16(acc[i][j], ah[i], bh[j]);
                MMA_BF16(acc[i][j], al[i], bh[j]);
                MMA_BF16(acc[i][j], ah[i], bl[j]);
            }
    }

    #pragma unroll
    for (int i = 0; i < 4; ++i)
        #pragma unroll
        for (int j = 0; j < 4; ++j) {
            int m = m0 + wm + i * 16 + gq;
            int n = n0 + wn + j * 8 + 2 * tg;
            float2 v0 = make_float2(acc[i][j][0], acc[i][j][1]);
            float2 v1 = make_float2(acc[i][j][2], acc[i][j][3]);
            if (BIAS) {
                float b0 = bias[n], b1 = bias[n + 1];
                v0.x += b0; v0.y += b1;
                v1.x += b0; v1.y += b1;
            }
            *(float2*)(C + (long)m * ldc + n)       = v0;
            *(float2*)(C + (long)(m + 8) * ldc + n) = v1;
        }
}

// ---------------- softmax over rows of length 512 ----------
__global__ void __launch_bounds__(128) softmax_k(float* __restrict__ S)
{
    float* p = S + (long)blockIdx.x * 512;
    int tid = threadIdx.x;
    float v[4];
    float m = -1e30f;
    #pragma unroll
    for (int i = 0; i < 4; ++i) { v[i] = p[tid + 128 * i] * 0.0625f; m = fmaxf(m, v[i]); }
    __shared__ float red[128];
    red[tid] = m; __syncthreads();
    for (int s = 64; s > 0; s >>= 1) { if (tid < s) red[tid] = fmaxf(red[tid], red[tid + s]); __syncthreads(); }
    m = red[0]; __syncthreads();
    float sum = 0.f;
    #pragma unroll
    for (int i = 0; i < 4; ++i) { v[i] = expf(v[i] - m); sum += v[i]; }
    red[tid] = sum; __syncthreads();
    for (int s = 64; s > 0; s >>= 1) { if (tid < s) red[tid] += red[tid + s]; __syncthreads(); }
    float inv = 1.f / red[0];
    #pragma unroll
    for (int i = 0; i < 4; ++i) p[tid + 128 * i] = v[i] * inv;
}

// ---------------- pack weights ----------------
__global__ void pack_init_k(const float* __restrict__ Wf, const float* __restrict__ Wi,
                            const float* __restrict__ Wu, const float* __restrict__ Wo,
                            const float* __restrict__ bf, const float* __restrict__ bi,
                            const float* __restrict__ bu, const float* __restrict__ bo)
{
    int idx = blockIdx.x * blockDim.x + threadIdx.x;
    int nt = gridDim.x * blockDim.x;
    // recurrent weights: [rank16][k256][jl16][g4]; col = rank*16 + jl
    for (int i = idx; i < CLU * 256 * 16 * 4; i += nt) {
        int r  = i >> 14;
        int k  = (i >> 6) & 255;
        int jl = (i >> 2) & 15;
        int g  = i & 3;
        const float* W = (g == 0) ? Wf : (g == 1) ? Wi : (g == 2) ? Wu : Wo;
        g_WhC[i] = W[(E_ + k) * H_ + r * 16 + jl];
    }
    for (int i = idx; i < 512 * 1024; i += nt) {
        int k = i >> 10;
        int col = i & 1023;
        int g = col >> 8, j = col & 255;
        const float* W = (g == 0) ? Wf : (g == 1) ? Wi : (g == 2) ? Wu : Wo;
        g_Wall[i] = W[k * 256 + j];
    }
    for (int i = idx; i < 1024; i += nt) {
        int g = i >> 8;
        const float* b = (g == 0) ? bf : (g == 1) ? bi : (g == 2) ? bu : bo;
        g_ball[i] = b[i & 255];
    }
}

__device__ __forceinline__ float sigf(float x)  { return 1.f / (1.f + __expf(-x)); }
__device__ __forceinline__ float tanhf_(float x){ return 2.f / (1.f + __expf(-2.f * x)) - 1.f; }

#define CARRIVE() asm volatile("barrier.cluster.arrive.aligned;" ::: "memory")
#define CWAIT()   asm volatile("barrier.cluster.wait.aligned;"   ::: "memory")

// ---------------- cluster LSTM recurrence: 16-CTA clusters, 2 quads ----------
// 8 clusters x 16 CTAs = 128 SMs. CTA rank owns 16 j-columns (64KB W in smem).
// part layout: fl4 part[ks*68 + b*16 + jl]  (epi reads 64 consecutive fl4)
__global__ void __launch_bounds__(256, 1) __cluster_dims__(CLU, 1, 1)
recur5_k(const float* __restrict__ PRE, float* __restrict__ out)
{
    extern __shared__ float4 sm4[];
    float4* ws4  = sm4;             // [256 k][16 jl] gate4     4096 fl4
    float4* hsA  = sm4 + 4096;      // [2 buf][256 j] b4         512 fl4
    float4* hsB  = sm4 + 4608;      // [2 buf][256 j] b4         512 fl4
    float4* part = sm4 + 5120;      // 16*68 = 1088 fl4

    const int tid = threadIdx.x;
    unsigned rank;
    asm("mov.u32 %0, %%cluster_ctarank;" : "=r"(rank));
    const int bg0 = (blockIdx.x >> 4) * BGR;

    const float4* Wsrc = (const float4*)g_WhC + (long)rank * 4096;
    for (int m = tid; m < 4096; m += 256) ws4[m] = Wsrc[m];
    for (int m = tid; m < 512; m += 256) {
        hsA[m] = make_float4(0.f, 0.f, 0.f, 0.f);
        hsB[m] = make_float4(0.f, 0.f, 0.f, 0.f);
    }

    const int jl = tid & 15;        // 0..15
    const int ks = tid >> 4;        // 0..15

    const bool epi = tid < 64;
    const int  eb  = tid & 3;
    const int  ejl = tid >> 2;      // 0..15
    const int  jg  = rank * 16 + ejl;

    float cA = 0.f, hA = 0.f, cB = 0.f, hB = 0.f;
    float pA0 = 0.f, pA1 = 0.f, pA2 = 0.f, pA3 = 0.f;
    float pB0 = 0.f, pB1 = 0.f, pB2 = 0.f, pB3 = 0.f;
    if (epi) {
        const float* pp = PRE + ((long)0 * B_ + bg0 + eb) * 1024 + jg;
        pA0 = pp[0]; pA1 = pp[256]; pA2 = pp[512]; pA3 = pp[768];
        const float* qq = PRE + ((long)0 * B_ + bg0 + 4 + eb) * 1024 + jg;
        pB0 = qq[0]; pB1 = qq[256]; pB2 = qq[512]; pB3 = qq[768];
    }

    const unsigned hsA_u32 = (unsigned)__cvta_generic_to_shared(hsA);
    const unsigned hsB_u32 = (unsigned)__cvta_generic_to_shared(hsB);

    __syncthreads();
    CARRIVE(); CWAIT();   // all CTAs' buffers zeroed before any publish
    CARRIVE();            // open pipeline phase

    for (int t = 0; t < T_; ++t) {
        const int buf = t & 1;

        // ---------- quad A ----------
        {
            const float4* hp = hsA + buf * 256 + ks * 16;
            const float4* wp = ws4 + (ks * 16) * 16 + jl;
            float4 a0 = {0,0,0,0}, a1 = {0,0,0,0}, a2 = {0,0,0,0}, a3 = {0,0,0,0};
            #pragma unroll 16
            for (int u = 0; u < 16; ++u) {
                float4 hv = hp[u];
                float4 wv = wp[u * 16];
                a0.x += hv.x*wv.x; a0.y += hv.x*wv.y; a0.z += hv.x*wv.z; a0.w += hv.x*wv.w;
                a1.x += hv.y*wv.x; a1.y += hv.y*wv.y; a1.z += hv.y*wv.z; a1.w += hv.y*wv.w;
                a2.x += hv.z*wv.x; a2.y += hv.z*wv.y; a2.z += hv.z*wv.z; a2.w += hv.z*wv.w;
                a3.x += hv.w*wv.x; a3.y += hv.w*wv.y; a3.z += hv.w*wv.z; a3.w += hv.w*wv.w;
            }
            part[ks * 68 + 0 * 16 + jl] = a0;
            part[ks * 68 + 1 * 16 + jl] = a1;
            part[ks * 68 + 2 * 16 + jl] = a2;
            part[ks * 68 + 3 * 16 + jl] = a3;
        }
        __syncthreads();
        if (epi) {
            float4 s = part[0 * 68 + eb * 16 + ejl];
            #pragma unroll
            for (int q = 1; q < 16; ++q) {
                float4 p = part[q * 68 + eb * 16 + ejl];
                s.x += p.x; s.y += p.y; s.z += p.z; s.w += p.w;
            }
            float fg = sigf  (s.x + pA0);
            float ig = sigf  (s.y + pA1);
            float ug = tanhf_(s.z + pA2);
            float og = sigf  (s.w + pA3);
            cA = fg * cA + ig * ug;
            hA = og * tanhf_(cA);
            out[((long)t * B_ + bg0 + eb) * H_ + jg] = hA;
            unsigned laddr = hsA_u32 + ((((buf ^ 1) * 256 + jg) * 4 + eb) << 2);
            #pragma unroll
            for (int r2 = 0; r2 < CLU; ++r2) {
                unsigned ra;
                asm volatile("mapa.shared::cluster.u32 %0, %1, %2;"
                             : "=r"(ra) : "r"(laddr), "r"(r2));
                asm volatile("st.shared::cluster.f32 [%0], %1;"
                             :: "r"(ra), "f"(hA) : "memory");
            }
            int tn = (t < T_ - 1) ? t + 1 : t;
            const float* pp = PRE + ((long)tn * B_ + bg0 + eb) * 1024 + jg;
            pA0 = pp[0]; pA1 = pp[256]; pA2 = pp[512]; pA3 = pp[768];
        }
        CWAIT();       // completes prior phase: hB(t) publishes visible
        CARRIVE();     // opens phase covering hA(t+1) publishes
        __syncthreads();

        // ---------- quad B ----------
        {
            const float4* hp = hsB + buf * 256 + ks * 16;
            const float4* wp = ws4 + (ks * 16) * 16 + jl;
            float4 a0 = {0,0,0,0}, a1 = {0,0,0,0}, a2 = {0,0,0,0}, a3 = {0,0,0,0};
            #pragma unroll 16
            for (int u = 0; u < 16; ++u) {
                float4 hv = hp[u];
                float4 wv = wp[u * 16];
                a0.x += hv.x*wv.x; a0.y += hv.x*wv.y; a0.z += hv.x*wv.z; a0.w += hv.x*wv.w;
                a1.x += hv.y*wv.x; a1.y += hv.y*wv.y; a1.z += hv.y*wv.z; a1.w += hv.y*wv.w;
                a2.x += hv.z*wv.x; a2.y += hv.z*wv.y; a2.z += hv.z*wv.z; a2.w += hv.z*wv.w;
                a3.x += hv.w*wv.x; a3.y += hv.w*wv.y; a3.z += hv.w*wv.z; a3.w += hv.w*wv.w;
            }
            part[ks * 68 + 0 * 16 + jl] = a0;
            part[ks * 68 + 1 * 16 + jl] = a1;
            part[ks * 68 + 2 * 16 + jl] = a2;
            part[ks * 68 + 3 * 16 + jl] = a3;
        }
        __syncthreads();
        if (epi) {
            float4 s = part[0 * 68 + eb * 16 + ejl];
            #pragma unroll
            for (int q = 1; q < 16; ++q) {
                float4 p = part[q * 68 + eb * 16 + ejl];
                s.x += p.x; s.y += p.y; s.z += p.z; s.w += p.w;
            }
            float fg = sigf  (s.x + pB0);
            float ig = sigf  (s.y + pB1);
            float ug = tanhf_(s.z + pB2);
            float og = sigf  (s.w + pB3);
            cB = fg * cB + ig * ug;
            hB = og * tanhf_(cB);
            out[((long)t * B_ + bg0 + 4 + eb) * H_ + jg] = hB;
            unsigned laddr = hsB_u32 + ((((buf ^ 1) * 256 + jg) * 4 + eb) << 2);
            #pragma unroll
            for (int r2 = 0; r2 < CLU; ++r2) {
                unsigned ra;
                asm volatile("mapa.shared::cluster.u32 %0, %1, %2;"
                             : "=r"(ra) : "r"(laddr), "r"(r2));
                asm volatile("st.shared::cluster.f32 [%0], %1;"
                             :: "r"(ra), "f"(hB) : "memory");
            }
            int tn = (t < T_ - 1) ? t + 1 : t;
            const float* qq = PRE + ((long)tn * B_ + bg0 + 4 + eb) * 1024 + jg;
            pB0 = qq[0]; pB1 = qq[256]; pB2 = qq[512]; pB3 = qq[768];
        }
        CWAIT();       // completes phase of hA(t+1)
        CARRIVE();     // opens phase covering hB(t+1)
        __syncthreads();
    }
    CWAIT();           // match final arrive

    if (epi) {
        out[(long)TB_ * H_ + (bg0 + eb) * H_ + jg] = hA;
        out[(long)TB_ * H_ + (bg0 + 4 + eb) * H_ + jg] = hB;
        out[(long)TB_ * H_ + (long)B_ * H_ + (bg0 + eb) * H_ + jg] = cA;
        out[(long)TB_ * H_ + (long)B_ * H_ + (bg0 + 4 + eb) * H_ + jg] = cB;
    }
}

// ---------------- launch ----------------
extern "C" void kernel_launch(void* const* d_in, const int* in_sizes, int n_in,
                              void* d_out, int out_size)
{
    const float* inputs = (const float*)d_in[0];
    const float* rot    = (const float*)d_in[1];
    const float* ent    = (const float*)d_in[2];
    const float* Wf = (const float*)d_in[3];  const float* bf = (const float*)d_in[4];
    const float* Wi = (const float*)d_in[5];  const float* bi = (const float*)d_in[6];
    const float* Wu = (const float*)d_in[7];  const float* bu = (const float*)d_in[8];
    const float* Wo = (const float*)d_in[9];  const float* bo = (const float*)d_in[10];
    const float* Wc = (const float*)d_in[11]; const float* bc = (const float*)d_in[12];
    float* out = (float*)d_out;

    float *Q, *K, *S, *CTX, *CP, *PRE, *Wall, *ball;
    cudaGetSymbolAddress((void**)&Q,    g_Q);
    cudaGetSymbolAddress((void**)&K,    g_K);
    cudaGetSymbolAddress((void**)&S,    g_S);
    cudaGetSymbolAddress((void**)&CTX,  g_CTX);
    cudaGetSymbolAddress((void**)&CP,   g_CP);
    cudaGetSymbolAddress((void**)&PRE,  g_PRE);
    cudaGetSymbolAddress((void**)&Wall, g_Wall);
    cudaGetSymbolAddress((void**)&ball, g_ball);

    const int RSMEM = (4096 + 512 + 512 + 1088) * 16;   // 99328 B
    cudaFuncSetAttribute(recur5_k, cudaFuncAttributeMaxDynamicSharedMemorySize, RSMEM);
    cudaFuncSetAttribute(recur5_k, cudaFuncAttributeNonPortableClusterSizeAllowed, 1);

    pack_init_k<<<256, 256>>>(Wf, Wi, Wu, Wo, bf, bi, bu, bo);

    // Q = X @ rot ; K = X @ ent
    gemm_tc<false, false, false><<<dim3(E_ / 128, TB_ / 128, 1), 256>>>(
        inputs, nullptr, rot, Q, nullptr, TB_, E_, E_, E_, E_, E_, 0, 0, 0);
    gemm_tc<false, false, false><<<dim3(E_ / 128, TB_ / 128, 1), 256>>>(
        inputs, nullptr, ent, K, nullptr, TB_, E_, E_, E_, E_, E_, 0, 0, 0);

    // scores_b = Q_b @ K_b^T
    gemm_tc<true, false, false><<<dim3(T_ / 128, T_ / 128, B_), 256>>>(
        Q, nullptr, K, S, nullptr, T_, T_, E_, B_ * E_, B_ * E_, T_,
        (long)E_, (long)E_, (long)T_ * T_);

    softmax_k<<<B_ * T_, 128>>>(S);

    // context_b = S_b @ X_b
    gemm_tc<false, false, false><<<dim3(E_ / 128, T_ / 128, B_), 256>>>(
        S, nullptr, inputs, CTX, nullptr, T_, E_, T_, T_, B_ * E_, B_ * E_,
        (long)T_ * T_, (long)E_, (long)E_);

    // CP = CTX @ Wc + bc
    gemm_tc<false, true, false><<<dim3(H_ / 128, TB_ / 128, 1), 256>>>(
        CTX, nullptr, Wc, CP, bc, TB_, H_, E_, E_, H_, H_, 0, 0, 0);

    // PRE = [X | CP] @ Wall + ball
    gemm_tc<false, true, true><<<dim3(1024 / 128, TB_ / 128, 1), 256>>>(
        inputs, CP, Wall, PRE, ball, TB_, 1024, 512, E_, 1024, 1024, 0, 0, 0);

    recur5_k<<<128, 256, RSMEM>>>(PRE, out);
    (void)in_sizes; (void)n_in; (void)out_size;
}

// round 8
// speedup vs baseline: 1.2588x; 1.2588x over previous
#include <cuda_runtime.h>
#include <math.h>

#define T_  512
#define B_  64
#define E_  256
#define H_  256
#define TB_ (T_ * B_)          // 32768
#define CLU 8                  // CTAs per cluster
#define BGR 8                  // batch elements per cluster (two quads)

// ---------------- static device scratch ----------------
__device__ float g_Q  [TB_ * E_];
__device__ float g_K  [TB_ * E_];
__device__ float g_S  [B_ * T_ * T_];
__device__ float g_CTX[TB_ * E_];
__device__ float g_CP [TB_ * H_];
__device__ float g_PRE[(long)TB_ * 4 * H_];
__device__ float g_Wall[512 * 1024];       // packed [Wf|Wi|Wu|Wo] as (512, 1024)
__device__ float g_ball[1024];
__device__ float g_WhC[CLU * 256 * 32 * 4];// recurrent W: [rank][k][jl][gate4]

// ---------------- bf16 2-split helpers ----------------
__device__ __forceinline__ void split_bf2(float e, float o, unsigned& hi, unsigned& lo)
{
    unsigned h;
    asm("cvt.rn.bf16x2.f32 %0, %1, %2;" : "=r"(h) : "f"(o), "f"(e));
    float eh = __uint_as_float(h << 16);
    float oh = __uint_as_float(h & 0xffff0000u);
    unsigned l;
    asm("cvt.rn.bf16x2.f32 %0, %1, %2;" : "=r"(l) : "f"(o - oh), "f"(e - eh));
    hi = h; lo = l;
}

#define MMA_BF16(c, a, b)                                                          \
    asm volatile("mma.sync.aligned.m16n8k16.row.col.f32.bf16.bf16.f32 "            \
                 "{%0,%1,%2,%3},{%4,%5,%6,%7},{%8,%9},{%0,%1,%2,%3};"              \
                 : "+f"(c[0]), "+f"(c[1]), "+f"(c[2]), "+f"(c[3])                  \
                 : "r"(a[0]), "r"(a[1]), "r"(a[2]), "r"(a[3]),                     \
                   "r"(b[0]), "r"(b[1]))

// ---------------- tensor-core bf16 GEMM, 128x128x16 tile, 3x split, occ 2 ----
template<bool NT, bool BIAS, bool CONCAT>
__global__ void __launch_bounds__(256, 2) gemm_tc(
    const float* __restrict__ A, const float* __restrict__ A2,
    const float* __restrict__ B, float* __restrict__ C,
    const float* __restrict__ bias,
    int M, int N, int K, int lda, int ldb, int ldc,
    long sA, long sB, long sC)
{
    A += (long)blockIdx.z * sA;
    B += (long)blockIdx.z * sB;
    C += (long)blockIdx.z * sC;

    __shared__ unsigned As_hi[8][136], As_lo[8][136];
    __shared__ unsigned Bs_hi[8][136], Bs_lo[8][136];

    const int tid  = threadIdx.x;
    const int lane = tid & 31;
    const int warp = tid >> 5;
    const int m0 = blockIdx.y * 128;
    const int n0 = blockIdx.x * 128;
    const int wm = (warp >> 2) * 64;
    const int wn = (warp & 3) * 32;
    const int gq = lane >> 2;
    const int tg = lane & 3;

    const int ar = tid & 127;
    const int aq = (tid >> 7) * 4;
    const int bkr = tid >> 5;
    const int bn  = (tid & 31) * 4;
    const int bn_t = tid & 127;
    const int bq   = (tid >> 7) * 4;

    float acc[4][4][4];
    #pragma unroll
    for (int i = 0; i < 4; ++i)
        #pragma unroll
        for (int j = 0; j < 4; ++j)
            #pragma unroll
            for (int q = 0; q < 4; ++q) acc[i][j][q] = 0.f;

    float4 va0, va1, vb0, vb1;
    auto load_tile = [&](int k0) {
        const float* Ab = A;
        int kc = k0;
        if (CONCAT) { if (k0 >= 256) { Ab = A2; kc = k0 - 256; } }
        va0 = *(const float4*)(Ab + (long)(m0 + ar) * lda + kc + aq);
        va1 = *(const float4*)(Ab + (long)(m0 + ar) * lda + kc + aq + 8);
        if (NT) {
            vb0 = *(const float4*)(B + (long)(n0 + bn_t) * ldb + k0 + bq);
            vb1 = *(const float4*)(B + (long)(n0 + bn_t) * ldb + k0 + bq + 8);
        } else {
            vb0 = *(const float4*)(B + (long)(k0 + 2 * bkr) * ldb + n0 + bn);
            vb1 = *(const float4*)(B + (long)(k0 + 2 * bkr + 1) * ldb + n0 + bn);
        }
    };

    load_tile(0);

    for (int k0 = 0; k0 < K; k0 += 16) {
        __syncthreads();
        {
            int kp = aq >> 1;
            split_bf2(va0.x, va0.y, As_hi[kp    ][ar], As_lo[kp    ][ar]);
            split_bf2(va0.z, va0.w, As_hi[kp + 1][ar], As_lo[kp + 1][ar]);
            split_bf2(va1.x, va1.y, As_hi[kp + 4][ar], As_lo[kp + 4][ar]);
            split_bf2(va1.z, va1.w, As_hi[kp + 5][ar], As_lo[kp + 5][ar]);
            if (NT) {
                int bp = bq >> 1;
                split_bf2(vb0.x, vb0.y, Bs_hi[bp    ][bn_t], Bs_lo[bp    ][bn_t]);
                split_bf2(vb0.z, vb0.w, Bs_hi[bp + 1][bn_t], Bs_lo[bp + 1][bn_t]);
                split_bf2(vb1.x, vb1.y, Bs_hi[bp + 4][bn_t], Bs_lo[bp + 4][bn_t]);
                split_bf2(vb1.z, vb1.w, Bs_hi[bp + 5][bn_t], Bs_lo[bp + 5][bn_t]);
            } else {
                uint4 h4, l4;
                split_bf2(vb0.x, vb1.x, h4.x, l4.x);
                split_bf2(vb0.y, vb1.y, h4.y, l4.y);
                split_bf2(vb0.z, vb1.z, h4.z, l4.z);
                split_bf2(vb0.w, vb1.w, h4.w, l4.w);
                *(uint4*)&Bs_hi[bkr][bn] = h4;
                *(uint4*)&Bs_lo[bkr][bn] = l4;
            }
        }
        __syncthreads();

        int kn = (k0 + 16 < K) ? k0 + 16 : k0;
        load_tile(kn);

        unsigned ah[4][4], al[4][4], bh[4][2], bl[4][2];
        #pragma unroll
        for (int i = 0; i < 4; ++i) {
            int r = wm + i * 16 + gq;
            ah[i][0] = As_hi[tg    ][r];
            ah[i][1] = As_hi[tg    ][r + 8];
            ah[i][2] = As_hi[tg + 4][r];
            ah[i][3] = As_hi[tg + 4][r + 8];
            al[i][0] = As_lo[tg    ][r];
            al[i][1] = As_lo[tg    ][r + 8];
            al[i][2] = As_lo[tg + 4][r];
            al[i][3] = As_lo[tg + 4][r + 8];
        }
        #pragma unroll
        for (int j = 0; j < 4; ++j) {
            int n = wn + j * 8 + gq;
            bh[j][0] = Bs_hi[tg    ][n];
            bh[j][1] = Bs_hi[tg + 4][n];
            bl[j][0] = Bs_lo[tg    ][n];
            bl[j][1] = Bs_lo[tg + 4][n];
        }
        #pragma unroll
        for (int i = 0; i < 4; ++i)
            #pragma unroll
            for (int j = 0; j < 4; ++j) {
                MMA_BF16(acc[i][j], ah[i], bh[j]);
                MMA_BF16(acc[i][j], al[i], bh[j]);
                MMA_BF16(acc[i][j], ah[i], bl[j]);
            }
    }

    #pragma unroll
    for (int i = 0; i < 4; ++i)
        #pragma unroll
        for (int j = 0; j < 4; ++j) {
            int m = m0 + wm + i * 16 + gq;
            int n = n0 + wn + j * 8 + 2 * tg;
            float2 v0 = make_float2(acc[i][j][0], acc[i][j][1]);
            float2 v1 = make_float2(acc[i][j][2], acc[i][j][3]);
            if (BIAS) {
                float b0 = bias[n], b1 = bias[n + 1];
                v0.x += b0; v0.y += b1;
                v1.x += b0; v1.y += b1;
            }
            *(float2*)(C + (long)m * ldc + n)       = v0;
            *(float2*)(C + (long)(m + 8) * ldc + n) = v1;
        }
}

// ---------------- softmax over rows of length 512 ----------
__global__ void __launch_bounds__(128) softmax_k(float* __restrict__ S)
{
    float* p = S + (long)blockIdx.x * 512;
    int tid = threadIdx.x;
    float v[4];
    float m = -1e30f;
    #pragma unroll
    for (int i = 0; i < 4; ++i) { v[i] = p[tid + 128 * i] * 0.0625f; m = fmaxf(m, v[i]); }
    __shared__ float red[128];
    red[tid] = m; __syncthreads();
    for (int s = 64; s > 0; s >>= 1) { if (tid < s) red[tid] = fmaxf(red[tid], red[tid + s]); __syncthreads(); }
    m = red[0]; __syncthreads();
    float sum = 0.f;
    #pragma unroll
    for (int i = 0; i < 4; ++i) { v[i] = expf(v[i] - m); sum += v[i]; }
    red[tid] = sum; __syncthreads();
    for (int s = 64; s > 0; s >>= 1) { if (tid < s) red[tid] += red[tid + s]; __syncthreads(); }
    float inv = 1.f / red[0];
    #pragma unroll
    for (int i = 0; i < 4; ++i) p[tid + 128 * i] = v[i] * inv;
}

// ---------------- pack weights ----------------
__global__ void pack_init_k(const float* __restrict__ Wf, const float* __restrict__ Wi,
                            const float* __restrict__ Wu, const float* __restrict__ Wo,
                            const float* __restrict__ bf, const float* __restrict__ bi,
                            const float* __restrict__ bu, const float* __restrict__ bo)
{
    int idx = blockIdx.x * blockDim.x + threadIdx.x;
    int nt = gridDim.x * blockDim.x;
    for (int i = idx; i < CLU * 256 * 32 * 4; i += nt) {
        int r  = i >> 15;
        int k  = (i >> 7) & 255;
        int jl = (i >> 2) & 31;
        int g  = i & 3;
        const float* W = (g == 0) ? Wf : (g == 1) ? Wi : (g == 2) ? Wu : Wo;
        g_WhC[i] = W[(E_ + k) * H_ + r * 32 + jl];
    }
    for (int i = idx; i < 512 * 1024; i += nt) {
        int k = i >> 10;
        int col = i & 1023;
        int g = col >> 8, j = col & 255;
        const float* W = (g == 0) ? Wf : (g == 1) ? Wi : (g == 2) ? Wu : Wo;
        g_Wall[i] = W[k * 256 + j];
    }
    for (int i = idx; i < 1024; i += nt) {
        int g = i >> 8;
        const float* b = (g == 0) ? bf : (g == 1) ? bi : (g == 2) ? bu : bo;
        g_ball[i] = b[i & 255];
    }
}

__device__ __forceinline__ float sigf(float x)  { return 1.f / (1.f + __expf(-x)); }
__device__ __forceinline__ float tanhf_(float x){ return 2.f / (1.f + __expf(-2.f * x)) - 1.f; }

#define CARRIVE() asm volatile("barrier.cluster.arrive.aligned;" ::: "memory")
#define CWAIT()   asm volatile("barrier.cluster.wait.aligned;"   ::: "memory")

// ---------------- cluster LSTM recurrence: one barrier pair per step ---------
// 8 clusters x 8 CTAs. Cluster owns 8 batches (quads A, B). Per step:
//   computeA; sync; epiA(publish); sync; computeB; sync; epiB(publish);
//   arrive; wait   <- single cluster barrier covers both quads' publishes.
// part layout: fl4 part[b*257 + ks*32 + jl] -> conflict-free store AND reduce.
__global__ void __launch_bounds__(256, 1) __cluster_dims__(CLU, 1, 1)
recur6_k(const float* __restrict__ PRE, float* __restrict__ out)
{
    extern __shared__ float4 sm4[];
    float4* ws4  = sm4;             // [256 k][32 jl] gate4     8192 fl4
    float4* hsA  = sm4 + 8192;      // [2 buf][256 j] b4         512 fl4
    float4* hsB  = sm4 + 8704;      // [2 buf][256 j] b4         512 fl4
    float4* part = sm4 + 9216;      // 4*257 = 1028 fl4

    const int tid = threadIdx.x;
    unsigned rank;
    asm("mov.u32 %0, %%cluster_ctarank;" : "=r"(rank));
    const int bg0 = (blockIdx.x >> 3) * BGR;

    const float4* Wsrc = (const float4*)g_WhC + (long)rank * 8192;
    for (int m = tid; m < 8192; m += 256) ws4[m] = Wsrc[m];
    for (int m = tid; m < 512; m += 256) {
        hsA[m] = make_float4(0.f, 0.f, 0.f, 0.f);
        hsB[m] = make_float4(0.f, 0.f, 0.f, 0.f);
    }

    const int jl = tid & 31;
    const int ks = tid >> 5;

    const bool epi = tid < 128;
    const int  eb  = tid & 3;
    const int  ejl = tid >> 2;
    const int  jg  = rank * 32 + ejl;

    float cA = 0.f, hA = 0.f, cB = 0.f, hB = 0.f;
    float pA0 = 0.f, pA1 = 0.f, pA2 = 0.f, pA3 = 0.f;
    float pB0 = 0.f, pB1 = 0.f, pB2 = 0.f, pB3 = 0.f;
    if (epi) {
        const float* pp = PRE + ((long)0 * B_ + bg0 + eb) * 1024 + jg;
        pA0 = pp[0]; pA1 = pp[256]; pA2 = pp[512]; pA3 = pp[768];
        const float* qq = PRE + ((long)0 * B_ + bg0 + 4 + eb) * 1024 + jg;
        pB0 = qq[0]; pB1 = qq[256]; pB2 = qq[512]; pB3 = qq[768];
    }

    const unsigned hsA_u32 = (unsigned)__cvta_generic_to_shared(hsA);
    const unsigned hsB_u32 = (unsigned)__cvta_generic_to_shared(hsB);

    __syncthreads();
    CARRIVE(); CWAIT();   // all CTAs' buffers zeroed before any publish

    for (int t = 0; t < T_; ++t) {
        const int buf = t & 1;

        // ---------- quad A compute ----------
        {
            const float4* hp = hsA + buf * 256 + ks * 32;
            const float4* wp = ws4 + (ks * 32) * 32 + jl;
            float4 a0 = {0,0,0,0}, a1 = {0,0,0,0}, a2 = {0,0,0,0}, a3 = {0,0,0,0};
            #pragma unroll 8
            for (int u = 0; u < 32; ++u) {
                float4 hv = hp[u];
                float4 wv = wp[u * 32];
                a0.x += hv.x*wv.x; a0.y += hv.x*wv.y; a0.z += hv.x*wv.z; a0.w += hv.x*wv.w;
                a1.x += hv.y*wv.x; a1.y += hv.y*wv.y; a1.z += hv.y*wv.z; a1.w += hv.y*wv.w;
                a2.x += hv.z*wv.x; a2.y += hv.z*wv.y; a2.z += hv.z*wv.z; a2.w += hv.z*wv.w;
                a3.x += hv.w*wv.x; a3.y += hv.w*wv.y; a3.z += hv.w*wv.z; a3.w += hv.w*wv.w;
            }
            part[0 * 257 + ks * 32 + jl] = a0;
            part[1 * 257 + ks * 32 + jl] = a1;
            part[2 * 257 + ks * 32 + jl] = a2;
            part[3 * 257 + ks * 32 + jl] = a3;
        }
        __syncthreads();
        // ---------- quad A epilogue ----------
        if (epi) {
            float4 s = part[eb * 257 + 0 * 32 + ejl];
            #pragma unroll
            for (int q = 1; q < 8; ++q) {
                float4 p = part[eb * 257 + q * 32 + ejl];
                s.x += p.x; s.y += p.y; s.z += p.z; s.w += p.w;
            }
            float fg = sigf  (s.x + pA0);
            float ig = sigf  (s.y + pA1);
            float ug = tanhf_(s.z + pA2);
            float og = sigf  (s.w + pA3);
            cA = fg * cA + ig * ug;
            hA = og * tanhf_(cA);
            out[((long)t * B_ + bg0 + eb) * H_ + jg] = hA;
            unsigned laddr = hsA_u32 + ((((buf ^ 1) * 256 + jg) * 4 + eb) << 2);
            #pragma unroll
            for (int r2 = 0; r2 < CLU; ++r2) {
                unsigned ra;
                asm volatile("mapa.shared::cluster.u32 %0, %1, %2;"
                             : "=r"(ra) : "r"(laddr), "r"(r2));
                asm volatile("st.shared::cluster.f32 [%0], %1;"
                             :: "r"(ra), "f"(hA) : "memory");
            }
            int tn = (t < T_ - 1) ? t + 1 : t;
            const float* pp = PRE + ((long)tn * B_ + bg0 + eb) * 1024 + jg;
            pA0 = pp[0]; pA1 = pp[256]; pA2 = pp[512]; pA3 = pp[768];
        }
        __syncthreads();   // part reuse by quad B

        // ---------- quad B compute ----------
        {
            const float4* hp = hsB + buf * 256 + ks * 32;
            const float4* wp = ws4 + (ks * 32) * 32 + jl;
            float4 a0 = {0,0,0,0}, a1 = {0,0,0,0}, a2 = {0,0,0,0}, a3 = {0,0,0,0};
            #pragma unroll 8
            for (int u = 0; u < 32; ++u) {
                float4 hv = hp[u];
                float4 wv = wp[u * 32];
                a0.x += hv.x*wv.x; a0.y += hv.x*wv.y; a0.z += hv.x*wv.z; a0.w += hv.x*wv.w;
                a1.x += hv.y*wv.x; a1.y += hv.y*wv.y; a1.z += hv.y*wv.z; a1.w += hv.y*wv.w;
                a2.x += hv.z*wv.x; a2.y += hv.z*wv.y; a2.z += hv.z*wv.z; a2.w += hv.z*wv.w;
                a3.x += hv.w*wv.x; a3.y += hv.w*wv.y; a3.z += hv.w*wv.z; a3.w += hv.w*wv.w;
            }
            part[0 * 257 + ks * 32 + jl] = a0;
            part[1 * 257 + ks * 32 + jl] = a1;
            part[2 * 257 + ks * 32 + jl] = a2;
            part[3 * 257 + ks * 32 + jl] = a3;
        }
        __syncthreads();
        // ---------- quad B epilogue ----------
        if (epi) {
            float4 s = part[eb * 257 + 0 * 32 + ejl];
            #pragma unroll
            for (int q = 1; q < 8; ++q) {
                float4 p = part[eb * 257 + q * 32 + ejl];
                s.x += p.x; s.y += p.y; s.z += p.z; s.w += p.w;
            }
            float fg = sigf  (s.x + pB0);
            float ig = sigf  (s.y + pB1);
            float ug = tanhf_(s.z + pB2);
            float og = sigf  (s.w + pB3);
            cB = fg * cB + ig * ug;
            hB = og * tanhf_(cB);
            out[((long)t * B_ + bg0 + 4 + eb) * H_ + jg] = hB;
            unsigned laddr = hsB_u32 + ((((buf ^ 1) * 256 + jg) * 4 + eb) << 2);
            #pragma unroll
            for (int r2 = 0; r2 < CLU; ++r2) {
                unsigned ra;
                asm volatile("mapa.shared::cluster.u32 %0, %1, %2;"
                             : "=r"(ra) : "r"(laddr), "r"(r2));
                asm volatile("st.shared::cluster.f32 [%0], %1;"
                             :: "r"(ra), "f"(hB) : "memory");
            }
            int tn = (t < T_ - 1) ? t + 1 : t;
            const float* qq = PRE + ((long)tn * B_ + bg0 + 4 + eb) * 1024 + jg;
            pB0 = qq[0]; pB1 = qq[256]; pB2 = qq[512]; pB3 = qq[768];
        }

        // single cluster barrier: all publishes (A and B) done everywhere
        CARRIVE();
        CWAIT();
    }

    if (epi) {
        out[(long)TB_ * H_ + (bg0 + eb) * H_ + jg] = hA;
        out[(long)TB_ * H_ + (bg0 + 4 + eb) * H_ + jg] = hB;
        out[(long)TB_ * H_ + (long)B_ * H_ + (bg0 + eb) * H_ + jg] = cA;
        out[(long)TB_ * H_ + (long)B_ * H_ + (bg0 + 4 + eb) * H_ + jg] = cB;
    }
}

// ---------------- launch ----------------
extern "C" void kernel_launch(void* const* d_in, const int* in_sizes, int n_in,
                              void* d_out, int out_size)
{
    const float* inputs = (const float*)d_in[0];
    const float* rot    = (const float*)d_in[1];
    const float* ent    = (const float*)d_in[2];
    const float* Wf = (const float*)d_in[3];  const float* bf = (const float*)d_in[4];
    const float* Wi = (const float*)d_in[5];  const float* bi = (const float*)d_in[6];
    const float* Wu = (const float*)d_in[7];  const float* bu = (const float*)d_in[8];
    const float* Wo = (const float*)d_in[9];  const float* bo = (const float*)d_in[10];
    const float* Wc = (const float*)d_in[11]; const float* bc = (const float*)d_in[12];
    float* out = (float*)d_out;

    float *Q, *K, *S, *CTX, *CP, *PRE, *Wall, *ball;
    cudaGetSymbolAddress((void**)&Q,    g_Q);
    cudaGetSymbolAddress((void**)&K,    g_K);
    cudaGetSymbolAddress((void**)&S,    g_S);
    cudaGetSymbolAddress((void**)&CTX,  g_CTX);
    cudaGetSymbolAddress((void**)&CP,   g_CP);
    cudaGetSymbolAddress((void**)&PRE,  g_PRE);
    cudaGetSymbolAddress((void**)&Wall, g_Wall);
    cudaGetSymbolAddress((void**)&ball, g_ball);

    const int RSMEM = (8192 + 512 + 512 + 1028) * 16;   // 163904 B
    cudaFuncSetAttribute(recur6_k, cudaFuncAttributeMaxDynamicSharedMemorySize, RSMEM);

    pack_init_k<<<256, 256>>>(Wf, Wi, Wu, Wo, bf, bi, bu, bo);

    // Q = X @ rot ; K = X @ ent
    gemm_tc<false, false, false><<<dim3(E_ / 128, TB_ / 128, 1), 256>>>(
        inputs, nullptr, rot, Q, nullptr, TB_, E_, E_, E_, E_, E_, 0, 0, 0);
    gemm_tc<false, false, false><<<dim3(E_ / 128, TB_ / 128, 1), 256>>>(
        inputs, nullptr, ent, K, nullptr, TB_, E_, E_, E_, E_, E_, 0, 0, 0);

    // scores_b = Q_b @ K_b^T
    gemm_tc<true, false, false><<<dim3(T_ / 128, T_ / 128, B_), 256>>>(
        Q, nullptr, K, S, nullptr, T_, T_, E_, B_ * E_, B_ * E_, T_,
        (long)E_, (long)E_, (long)T_ * T_);

    softmax_k<<<B_ * T_, 128>>>(S);

    // context_b = S_b @ X_b
    gemm_tc<false, false, false><<<dim3(E_ / 128, T_ / 128, B_), 256>>>(
        S, nullptr, inputs, CTX, nullptr, T_, E_, T_, T_, B_ * E_, B_ * E_,
        (long)T_ * T_, (long)E_, (long)E_);

    // CP = CTX @ Wc + bc
    gemm_tc<false, true, false><<<dim3(H_ / 128, TB_ / 128, 1), 256>>>(
        CTX, nullptr, Wc, CP, bc, TB_, H_, E_, E_, H_, H_, 0, 0, 0);

    // PRE = [X | CP] @ Wall + ball
    gemm_tc<false, true, true><<<dim3(1024 / 128, TB_ / 128, 1), 256>>>(
        inputs, CP, Wall, PRE, ball, TB_, 1024, 512, E_, 1024, 1024, 0, 0, 0);

    recur6_k<<<64, 256, RSMEM>>>(PRE, out);
    (void)in_sizes; (void)n_in; (void)out_size;
}

// round 9
// speedup vs baseline: 1.2589x; 1.0000x over previous
#include <cuda_runtime.h>
#include <math.h>

#define T_  512
#define B_  64
#define E_  256
#define H_  256
#define TB_ (T_ * B_)          // 32768
#define CLU 8                  // CTAs per cluster
#define BGR 8                  // batch elements per cluster (two quads)

// ---------------- static device scratch ----------------
__device__ float g_Q  [TB_ * E_];
__device__ float g_K  [TB_ * E_];
__device__ float g_S  [B_ * T_ * T_];
__device__ float g_CTX[TB_ * E_];
__device__ float g_CP [TB_ * H_];
__device__ float g_PRE[(long)TB_ * 4 * H_];
__device__ float g_Wall[512 * 1024];       // packed [Wf|Wi|Wu|Wo] as (512, 1024)
__device__ float g_ball[1024];
__device__ float g_WhC[CLU * 256 * 32 * 4];// recurrent W: [rank][k][jl][gate4]

// ---------------- bf16 2-split helpers ----------------
__device__ __forceinline__ void split_bf2(float e, float o, unsigned& hi, unsigned& lo)
{
    unsigned h;
    asm("cvt.rn.bf16x2.f32 %0, %1, %2;" : "=r"(h) : "f"(o), "f"(e));
    float eh = __uint_as_float(h << 16);
    float oh = __uint_as_float(h & 0xffff0000u);
    unsigned l;
    asm("cvt.rn.bf16x2.f32 %0, %1, %2;" : "=r"(l) : "f"(o - oh), "f"(e - eh));
    hi = h; lo = l;
}

#define MMA_BF16(c, a, b)                                                          \
    asm volatile("mma.sync.aligned.m16n8k16.row.col.f32.bf16.bf16.f32 "            \
                 "{%0,%1,%2,%3},{%4,%5,%6,%7},{%8,%9},{%0,%1,%2,%3};"              \
                 : "+f"(c[0]), "+f"(c[1]), "+f"(c[2]), "+f"(c[3])                  \
                 : "r"(a[0]), "r"(a[1]), "r"(a[2]), "r"(a[3]),                     \
                   "r"(b[0]), "r"(b[1]))

// ------ tensor-core bf16 GEMM, 128x128x16 tile, 3x split, 2-stage pipeline ---
// One __syncthreads per k-tile: split of tile i+1 overlaps MMA of tile i.
template<bool NT, bool BIAS, bool CONCAT>
__global__ void __launch_bounds__(256, 2) gemm_tc(
    const float* __restrict__ A, const float* __restrict__ A2,
    const float* __restrict__ B, float* __restrict__ C,
    const float* __restrict__ bias,
    int M, int N, int K, int lda, int ldb, int ldc,
    long sA, long sB, long sC)
{
    A += (long)blockIdx.z * sA;
    B += (long)blockIdx.z * sB;
    C += (long)blockIdx.z * sC;

    __shared__ unsigned As_hi[2][8][136], As_lo[2][8][136];
    __shared__ unsigned Bs_hi[2][8][136], Bs_lo[2][8][136];

    const int tid  = threadIdx.x;
    const int lane = tid & 31;
    const int warp = tid >> 5;
    const int m0 = blockIdx.y * 128;
    const int n0 = blockIdx.x * 128;
    const int wm = (warp >> 2) * 64;
    const int wn = (warp & 3) * 32;
    const int gq = lane >> 2;
    const int tg = lane & 3;

    const int ar = tid & 127;
    const int aq = (tid >> 7) * 4;
    const int bkr = tid >> 5;
    const int bn  = (tid & 31) * 4;
    const int bn_t = tid & 127;
    const int bq   = (tid >> 7) * 4;

    float acc[4][4][4];
    #pragma unroll
    for (int i = 0; i < 4; ++i)
        #pragma unroll
        for (int j = 0; j < 4; ++j)
            #pragma unroll
            for (int q = 0; q < 4; ++q) acc[i][j][q] = 0.f;

    float4 va0, va1, vb0, vb1;
    auto load_tile = [&](int k0) {
        const float* Ab = A;
        int kc = k0;
        if (CONCAT) { if (k0 >= 256) { Ab = A2; kc = k0 - 256; } }
        va0 = *(const float4*)(Ab + (long)(m0 + ar) * lda + kc + aq);
        va1 = *(const float4*)(Ab + (long)(m0 + ar) * lda + kc + aq + 8);
        if (NT) {
            vb0 = *(const float4*)(B + (long)(n0 + bn_t) * ldb + k0 + bq);
            vb1 = *(const float4*)(B + (long)(n0 + bn_t) * ldb + k0 + bq + 8);
        } else {
            vb0 = *(const float4*)(B + (long)(k0 + 2 * bkr) * ldb + n0 + bn);
            vb1 = *(const float4*)(B + (long)(k0 + 2 * bkr + 1) * ldb + n0 + bn);
        }
    };

    auto split_store = [&](int s) {
        int kp = aq >> 1;
        split_bf2(va0.x, va0.y, As_hi[s][kp    ][ar], As_lo[s][kp    ][ar]);
        split_bf2(va0.z, va0.w, As_hi[s][kp + 1][ar], As_lo[s][kp + 1][ar]);
        split_bf2(va1.x, va1.y, As_hi[s][kp + 4][ar], As_lo[s][kp + 4][ar]);
        split_bf2(va1.z, va1.w, As_hi[s][kp + 5][ar], As_lo[s][kp + 5][ar]);
        if (NT) {
            int bp = bq >> 1;
            split_bf2(vb0.x, vb0.y, Bs_hi[s][bp    ][bn_t], Bs_lo[s][bp    ][bn_t]);
            split_bf2(vb0.z, vb0.w, Bs_hi[s][bp + 1][bn_t], Bs_lo[s][bp + 1][bn_t]);
            split_bf2(vb1.x, vb1.y, Bs_hi[s][bp + 4][bn_t], Bs_lo[s][bp + 4][bn_t]);
            split_bf2(vb1.z, vb1.w, Bs_hi[s][bp + 5][bn_t], Bs_lo[s][bp + 5][bn_t]);
        } else {
            uint4 h4, l4;
            split_bf2(vb0.x, vb1.x, h4.x, l4.x);
            split_bf2(vb0.y, vb1.y, h4.y, l4.y);
            split_bf2(vb0.z, vb1.z, h4.z, l4.z);
            split_bf2(vb0.w, vb1.w, h4.w, l4.w);
            *(uint4*)&Bs_hi[s][bkr][bn] = h4;
            *(uint4*)&Bs_lo[s][bkr][bn] = l4;
        }
    };

    load_tile(0);
    split_store(0);
    __syncthreads();

    const int nk = K >> 4;
    for (int it = 0; it < nk; ++it) {
        const int s = it & 1;
        if (it + 1 < nk) load_tile((it + 1) << 4);

        unsigned ah[4][4], al[4][4], bh[4][2], bl[4][2];
        #pragma unroll
        for (int i = 0; i < 4; ++i) {
            int r = wm + i * 16 + gq;
            ah[i][0] = As_hi[s][tg    ][r];
            ah[i][1] = As_hi[s][tg    ][r + 8];
            ah[i][2] = As_hi[s][tg + 4][r];
            ah[i][3] = As_hi[s][tg + 4][r + 8];
            al[i][0] = As_lo[s][tg    ][r];
            al[i][1] = As_lo[s][tg    ][r + 8];
            al[i][2] = As_lo[s][tg + 4][r];
            al[i][3] = As_lo[s][tg + 4][r + 8];
        }
        #pragma unroll
        for (int j = 0; j < 4; ++j) {
            int n = wn + j * 8 + gq;
            bh[j][0] = Bs_hi[s][tg    ][n];
            bh[j][1] = Bs_hi[s][tg + 4][n];
            bl[j][0] = Bs_lo[s][tg    ][n];
            bl[j][1] = Bs_lo[s][tg + 4][n];
        }
        #pragma unroll
        for (int i = 0; i < 4; ++i)
            #pragma unroll
            for (int j = 0; j < 4; ++j) {
                MMA_BF16(acc[i][j], ah[i], bh[j]);
                MMA_BF16(acc[i][j], al[i], bh[j]);
                MMA_BF16(acc[i][j], ah[i], bl[j]);
            }

        if (it + 1 < nk) split_store(s ^ 1);
        __syncthreads();
    }

    #pragma unroll
    for (int i = 0; i < 4; ++i)
        #pragma unroll
        for (int j = 0; j < 4; ++j) {
            int m = m0 + wm + i * 16 + gq;
            int n = n0 + wn + j * 8 + 2 * tg;
            float2 v0 = make_float2(acc[i][j][0], acc[i][j][1]);
            float2 v1 = make_float2(acc[i][j][2], acc[i][j][3]);
            if (BIAS) {
                float b0 = bias[n], b1 = bias[n + 1];
                v0.x += b0; v0.y += b1;
                v1.x += b0; v1.y += b1;
            }
            *(float2*)(C + (long)m * ldc + n)       = v0;
            *(float2*)(C + (long)(m + 8) * ldc + n) = v1;
        }
}

// ---------------- softmax over rows of length 512 ----------
__global__ void __launch_bounds__(128) softmax_k(float* __restrict__ S)
{
    float* p = S + (long)blockIdx.x * 512;
    int tid = threadIdx.x;
    float v[4];
    float m = -1e30f;
    #pragma unroll
    for (int i = 0; i < 4; ++i) { v[i] = p[tid + 128 * i] * 0.0625f; m = fmaxf(m, v[i]); }
    __shared__ float red[128];
    red[tid] = m; __syncthreads();
    for (int s = 64; s > 0; s >>= 1) { if (tid < s) red[tid] = fmaxf(red[tid], red[tid + s]); __syncthreads(); }
    m = red[0]; __syncthreads();
    float sum = 0.f;
    #pragma unroll
    for (int i = 0; i < 4; ++i) { v[i] = expf(v[i] - m); sum += v[i]; }
    red[tid] = sum; __syncthreads();
    for (int s = 64; s > 0; s >>= 1) { if (tid < s) red[tid] += red[tid + s]; __syncthreads(); }
    float inv = 1.f / red[0];
    #pragma unroll
    for (int i = 0; i < 4; ++i) p[tid + 128 * i] = v[i] * inv;
}

// ---------------- pack weights ----------------
__global__ void pack_init_k(const float* __restrict__ Wf, const float* __restrict__ Wi,
                            const float* __restrict__ Wu, const float* __restrict__ Wo,
                            const float* __restrict__ bf, const float* __restrict__ bi,
                            const float* __restrict__ bu, const float* __restrict__ bo)
{
    int idx = blockIdx.x * blockDim.x + threadIdx.x;
    int nt = gridDim.x * blockDim.x;
    for (int i = idx; i < CLU * 256 * 32 * 4; i += nt) {
        int r  = i >> 15;
        int k  = (i >> 7) & 255;
        int jl = (i >> 2) & 31;
        int g  = i & 3;
        const float* W = (g == 0) ? Wf : (g == 1) ? Wi : (g == 2) ? Wu : Wo;
        g_WhC[i] = W[(E_ + k) * H_ + r * 32 + jl];
    }
    for (int i = idx; i < 512 * 1024; i += nt) {
        int k = i >> 10;
        int col = i & 1023;
        int g = col >> 8, j = col & 255;
        const float* W = (g == 0) ? Wf : (g == 1) ? Wi : (g == 2) ? Wu : Wo;
        g_Wall[i] = W[k * 256 + j];
    }
    for (int i = idx; i < 1024; i += nt) {
        int g = i >> 8;
        const float* b = (g == 0) ? bf : (g == 1) ? bi : (g == 2) ? bu : bo;
        g_ball[i] = b[i & 255];
    }
}

__device__ __forceinline__ float sigf(float x)  { return 1.f / (1.f + __expf(-x)); }
__device__ __forceinline__ float tanhf_(float x){ return 2.f / (1.f + __expf(-2.f * x)) - 1.f; }

#define CARRIVE() asm volatile("barrier.cluster.arrive.aligned;" ::: "memory")
#define CWAIT()   asm volatile("barrier.cluster.wait.aligned;"   ::: "memory")

// ---------------- cluster LSTM recurrence (proven R8: one barrier per step) --
__global__ void __launch_bounds__(256, 1) __cluster_dims__(CLU, 1, 1)
recur6_k(const float* __restrict__ PRE, float* __restrict__ out)
{
    extern __shared__ float4 sm4[];
    float4* ws4  = sm4;             // [256 k][32 jl] gate4     8192 fl4
    float4* hsA  = sm4 + 8192;      // [2 buf][256 j] b4         512 fl4
    float4* hsB  = sm4 + 8704;      // [2 buf][256 j] b4         512 fl4
    float4* part = sm4 + 9216;      // 4*257 = 1028 fl4

    const int tid = threadIdx.x;
    unsigned rank;
    asm("mov.u32 %0, %%cluster_ctarank;" : "=r"(rank));
    const int bg0 = (blockIdx.x >> 3) * BGR;

    const float4* Wsrc = (const float4*)g_WhC + (long)rank * 8192;
    for (int m = tid; m < 8192; m += 256) ws4[m] = Wsrc[m];
    for (int m = tid; m < 512; m += 256) {
        hsA[m] = make_float4(0.f, 0.f, 0.f, 0.f);
        hsB[m] = make_float4(0.f, 0.f, 0.f, 0.f);
    }

    const int jl = tid & 31;
    const int ks = tid >> 5;

    const bool epi = tid < 128;
    const int  eb  = tid & 3;
    const int  ejl = tid >> 2;
    const int  jg  = rank * 32 + ejl;

    float cA = 0.f, hA = 0.f, cB = 0.f, hB = 0.f;
    float pA0 = 0.f, pA1 = 0.f, pA2 = 0.f, pA3 = 0.f;
    float pB0 = 0.f, pB1 = 0.f, pB2 = 0.f, pB3 = 0.f;
    if (epi) {
        const float* pp = PRE + ((long)0 * B_ + bg0 + eb) * 1024 + jg;
        pA0 = pp[0]; pA1 = pp[256]; pA2 = pp[512]; pA3 = pp[768];
        const float* qq = PRE + ((long)0 * B_ + bg0 + 4 + eb) * 1024 + jg;
        pB0 = qq[0]; pB1 = qq[256]; pB2 = qq[512]; pB3 = qq[768];
    }

    const unsigned hsA_u32 = (unsigned)__cvta_generic_to_shared(hsA);
    const unsigned hsB_u32 = (unsigned)__cvta_generic_to_shared(hsB);

    __syncthreads();
    CARRIVE(); CWAIT();

    for (int t = 0; t < T_; ++t) {
        const int buf = t & 1;

        // ---------- quad A compute ----------
        {
            const float4* hp = hsA + buf * 256 + ks * 32;
            const float4* wp = ws4 + (ks * 32) * 32 + jl;
            float4 a0 = {0,0,0,0}, a1 = {0,0,0,0}, a2 = {0,0,0,0}, a3 = {0,0,0,0};
            #pragma unroll 8
            for (int u = 0; u < 32; ++u) {
                float4 hv = hp[u];
                float4 wv = wp[u * 32];
                a0.x += hv.x*wv.x; a0.y += hv.x*wv.y; a0.z += hv.x*wv.z; a0.w += hv.x*wv.w;
                a1.x += hv.y*wv.x; a1.y += hv.y*wv.y; a1.z += hv.y*wv.z; a1.w += hv.y*wv.w;
                a2.x += hv.z*wv.x; a2.y += hv.z*wv.y; a2.z += hv.z*wv.z; a2.w += hv.z*wv.w;
                a3.x += hv.w*wv.x; a3.y += hv.w*wv.y; a3.z += hv.w*wv.z; a3.w += hv.w*wv.w;
            }
            part[0 * 257 + ks * 32 + jl] = a0;
            part[1 * 257 + ks * 32 + jl] = a1;
            part[2 * 257 + ks * 32 + jl] = a2;
            part[3 * 257 + ks * 32 + jl] = a3;
        }
        __syncthreads();
        if (epi) {
            float4 s = part[eb * 257 + 0 * 32 + ejl];
            #pragma unroll
            for (int q = 1; q < 8; ++q) {
                float4 p = part[eb * 257 + q * 32 + ejl];
                s.x += p.x; s.y += p.y; s.z += p.z; s.w += p.w;
            }
            float fg = sigf  (s.x + pA0);
            float ig = sigf  (s.y + pA1);
            float ug = tanhf_(s.z + pA2);
            float og = sigf  (s.w + pA3);
            cA = fg * cA + ig * ug;
            hA = og * tanhf_(cA);
            out[((long)t * B_ + bg0 + eb) * H_ + jg] = hA;
            unsigned laddr = hsA_u32 + ((((buf ^ 1) * 256 + jg) * 4 + eb) << 2);
            #pragma unroll
            for (int r2 = 0; r2 < CLU; ++r2) {
                unsigned ra;
                asm volatile("mapa.shared::cluster.u32 %0, %1, %2;"
                             : "=r"(ra) : "r"(laddr), "r"(r2));
                asm volatile("st.shared::cluster.f32 [%0], %1;"
                             :: "r"(ra), "f"(hA) : "memory");
            }
            int tn = (t < T_ - 1) ? t + 1 : t;
            const float* pp = PRE + ((long)tn * B_ + bg0 + eb) * 1024 + jg;
            pA0 = pp[0]; pA1 = pp[256]; pA2 = pp[512]; pA3 = pp[768];
        }
        __syncthreads();

        // ---------- quad B compute ----------
        {
            const float4* hp = hsB + buf * 256 + ks * 32;
            const float4* wp = ws4 + (ks * 32) * 32 + jl;
            float4 a0 = {0,0,0,0}, a1 = {0,0,0,0}, a2 = {0,0,0,0}, a3 = {0,0,0,0};
            #pragma unroll 8
            for (int u = 0; u < 32; ++u) {
                float4 hv = hp[u];
                float4 wv = wp[u * 32];
                a0.x += hv.x*wv.x; a0.y += hv.x*wv.y; a0.z += hv.x*wv.z; a0.w += hv.x*wv.w;
                a1.x += hv.y*wv.x; a1.y += hv.y*wv.y; a1.z += hv.y*wv.z; a1.w += hv.y*wv.w;
                a2.x += hv.z*wv.x; a2.y += hv.z*wv.y; a2.z += hv.z*wv.z; a2.w += hv.z*wv.w;
                a3.x += hv.w*wv.x; a3.y += hv.w*wv.y; a3.z += hv.w*wv.z; a3.w += hv.w*wv.w;
            }
            part[0 * 257 + ks * 32 + jl] = a0;
            part[1 * 257 + ks * 32 + jl] = a1;
            part[2 * 257 + ks * 32 + jl] = a2;
            part[3 * 257 + ks * 32 + jl] = a3;
        }
        __syncthreads();
        if (epi) {
            float4 s = part[eb * 257 + 0 * 32 + ejl];
            #pragma unroll
            for (int q = 1; q < 8; ++q) {
                float4 p = part[eb * 257 + q * 32 + ejl];
                s.x += p.x; s.y += p.y; s.z += p.z; s.w += p.w;
            }
            float fg = sigf  (s.x + pB0);
            float ig = sigf  (s.y + pB1);
            float ug = tanhf_(s.z + pB2);
            float og = sigf  (s.w + pB3);
            cB = fg * cB + ig * ug;
            hB = og * tanhf_(cB);
            out[((long)t * B_ + bg0 + 4 + eb) * H_ + jg] = hB;
            unsigned laddr = hsB_u32 + ((((buf ^ 1) * 256 + jg) * 4 + eb) << 2);
            #pragma unroll
            for (int r2 = 0; r2 < CLU; ++r2) {
                unsigned ra;
                asm volatile("mapa.shared::cluster.u32 %0, %1, %2;"
                             : "=r"(ra) : "r"(laddr), "r"(r2));
                asm volatile("st.shared::cluster.f32 [%0], %1;"
                             :: "r"(ra), "f"(hB) : "memory");
            }
            int tn = (t < T_ - 1) ? t + 1 : t;
            const float* qq = PRE + ((long)tn * B_ + bg0 + 4 + eb) * 1024 + jg;
            pB0 = qq[0]; pB1 = qq[256]; pB2 = qq[512]; pB3 = qq[768];
        }

        CARRIVE();
        CWAIT();
    }

    if (epi) {
        out[(long)TB_ * H_ + (bg0 + eb) * H_ + jg] = hA;
        out[(long)TB_ * H_ + (bg0 + 4 + eb) * H_ + jg] = hB;
        out[(long)TB_ * H_ + (long)B_ * H_ + (bg0 + eb) * H_ + jg] = cA;
        out[(long)TB_ * H_ + (long)B_ * H_ + (bg0 + 4 + eb) * H_ + jg] = cB;
    }
}

// ---------------- launch ----------------
extern "C" void kernel_launch(void* const* d_in, const int* in_sizes, int n_in,
                              void* d_out, int out_size)
{
    const float* inputs = (const float*)d_in[0];
    const float* rot    = (const float*)d_in[1];
    const float* ent    = (const float*)d_in[2];
    const float* Wf = (const float*)d_in[3];  const float* bf = (const float*)d_in[4];
    const float* Wi = (const float*)d_in[5];  const float* bi = (const float*)d_in[6];
    const float* Wu = (const float*)d_in[7];  const float* bu = (const float*)d_in[8];
    const float* Wo = (const float*)d_in[9];  const float* bo = (const float*)d_in[10];
    const float* Wc = (const float*)d_in[11]; const float* bc = (const float*)d_in[12];
    float* out = (float*)d_out;

    float *Q, *K, *S, *CTX, *CP, *PRE, *Wall, *ball;
    cudaGetSymbolAddress((void**)&Q,    g_Q);
    cudaGetSymbolAddress((void**)&K,    g_K);
    cudaGetSymbolAddress((void**)&S,    g_S);
    cudaGetSymbolAddress((void**)&CTX,  g_CTX);
    cudaGetSymbolAddress((void**)&CP,   g_CP);
    cudaGetSymbolAddress((void**)&PRE,  g_PRE);
    cudaGetSymbolAddress((void**)&Wall, g_Wall);
    cudaGetSymbolAddress((void**)&ball, g_ball);

    const int RSMEM = (8192 + 512 + 512 + 1028) * 16;
    cudaFuncSetAttribute(recur6_k, cudaFuncAttributeMaxDynamicSharedMemorySize, RSMEM);

    pack_init_k<<<256, 256>>>(Wf, Wi, Wu, Wo, bf, bi, bu, bo);

    // Q = X @ rot ; K = X @ ent
    gemm_tc<false, false, false><<<dim3(E_ / 128, TB_ / 128, 1), 256>>>(
        inputs, nullptr, rot, Q, nullptr, TB_, E_, E_, E_, E_, E_, 0, 0, 0);
    gemm_tc<false, false, false><<<dim3(E_ / 128, TB_ / 128, 1), 256>>>(
        inputs, nullptr, ent, K, nullptr, TB_, E_, E_, E_, E_, E_, 0, 0, 0);

    // scores_b = Q_b @ K_b^T
    gemm_tc<true, false, false><<<dim3(T_ / 128, T_ / 128, B_), 256>>>(
        Q, nullptr, K, S, nullptr, T_, T_, E_, B_ * E_, B_ * E_, T_,
        (long)E_, (long)E_, (long)T_ * T_);

    softmax_k<<<B_ * T_, 128>>>(S);

    // context_b = S_b @ X_b
    gemm_tc<false, false, false><<<dim3(E_ / 128, T_ / 128, B_), 256>>>(
        S, nullptr, inputs, CTX, nullptr, T_, E_, T_, T_, B_ * E_, B_ * E_,
        (long)T_ * T_, (long)E_, (long)E_);

    // CP = CTX @ Wc + bc
    gemm_tc<false, true, false><<<dim3(H_ / 128, TB_ / 128, 1), 256>>>(
        CTX, nullptr, Wc, CP, bc, TB_, H_, E_, E_, H_, H_, 0, 0, 0);

    // PRE = [X | CP] @ Wall + ball
    gemm_tc<false, true, true><<<dim3(1024 / 128, TB_ / 128, 1), 256>>>(
        inputs, CP, Wall, PRE, ball, TB_, 1024, 512, E_, 1024, 1024, 0, 0, 0);

    recur6_k<<<64, 256, RSMEM>>>(PRE, out);
    (void)in_sizes; (void)n_in; (void)out_size;
}